// round 10
// baseline (speedup 1.0000x reference)
#include <cuda_runtime.h>
#include <cuda_bf16.h>
#include <math.h>

// Problem constants
#define B_ 2
#define S_ 4096
#define H_ 16
#define DK 128
#define DV 128
#define CHK 64
#define NCH (S_ / CHK)          // 64 chunks
#define NBH (B_ * H_)           // 32
#define NTILE (NBH * NCH)       // 2048 tiles

typedef unsigned long long u64;

// packed f32x2 FMA (sm_100+): 2 lane-FMAs per instruction
__device__ __forceinline__ u64 ffma2(u64 a, u64 b, u64 c) {
    u64 d;
    asm("fma.rn.f32x2 %0, %1, %2, %3;" : "=l"(d) : "l"(a), "l"(b), "l"(c));
    return d;
}
__device__ __forceinline__ float fold2(u64 v) {
    float x, y;
    asm("mov.b64 {%0,%1}, %2;" : "=f"(x), "=f"(y) : "l"(v));
    return x + y;
}

// Scratch (device globals: allocation-free rule)
__device__ float g_u   [NTILE * CHK * DV];   // 64 MB
__device__ float g_kcd [NTILE * CHK * DK];   // 64 MB  (stored NEGATED)
__device__ float g_qg  [NTILE * CHK * DK];   // 64 MB
__device__ float g_kd  [NTILE * CHK * DK];   // 64 MB, pair-over-c: (c>>1)*256 + 2k + (c&1)
__device__ float g_attn[NTILE * CHK * CHK];  // 32 MB
__device__ float g_egl [NTILE];              // exp(g_last) per tile

#define SKP 130   // sk pitch: even (8B-aligned float2 column loads), low conflict

// p1 smem: sq 8192 + sk 8320 + sv 8192 + sAp 2080 + misc 576 = 27360 floats = 109,440 B
#define P1_SMEM_FLOATS (8192 + 8320 + 8192 + 2080 + 576)

// ---------------------------------------------------------------------------
// Phase 1: per-(b,h,chunk) preprocessing. grid = 2048, block = 256, 2 CTAs/SM.
// ---------------------------------------------------------------------------
__global__ __launch_bounds__(256, 2)
void p1_kernel(const float* __restrict__ q_in, const float* __restrict__ k_in,
               const float* __restrict__ v_in, const float* __restrict__ g_in,
               const float* __restrict__ b_in)
{
    extern __shared__ float sm[];
    float* sq   = sm;              // [64][128]  raw q; later kcd solve buffer
    float* sk   = sq + 8192;       // [64][SKP]  raw k
    float* sv   = sk + 8320;       // [64][128]  raw v; later u solve buffer
    float* sAp  = sv + 8192;       // packed strict-lower A: sAp[i*(i-1)/2 + j]
    float* s_g    = sAp + 2080;    // 64
    float* s_beta = s_g + 64;      // 64
    float* s_gcs  = s_beta + 64;   // 64
    float* s_fA   = s_gcs + 64;    // 64  rnq*Dk^-.5*e^{gcs}
    float* s_fB   = s_fA + 64;     // 64  rnk*e^{-gcs}
    float* s_gA   = s_fB + 64;     // 64  rnk*beta*e^{gcs}
    float* s_fKD  = s_gA + 64;     // 64  fB*e^{gcs63}
    float* s_rn   = s_fKD + 64;    // 128: [0..63] rnq*Dk^-.5, [64..127] rnk

    const int t   = blockIdx.x;
    const int n   = t & (NCH - 1);
    const int bh  = t >> 6;
    const int b   = bh >> 4;
    const int h   = bh & 15;
    const int tid = threadIdx.x;

    const size_t base = ((size_t)(b * S_ + n * CHK) * H_ + h) * DK;

    // Load raw q/k/v tile
    for (int p = tid; p < 2048; p += 256) {
        int row = p >> 5;
        int c   = (p & 31) * 4;
        float4 qv = *(const float4*)&q_in[base + (size_t)row * 2048 + c];
        float4 kv = *(const float4*)&k_in[base + (size_t)row * 2048 + c];
        float4 vv = *(const float4*)&v_in[base + (size_t)row * 2048 + c];
        sq[row * 128 + c + 0] = qv.x; sq[row * 128 + c + 1] = qv.y;
        sq[row * 128 + c + 2] = qv.z; sq[row * 128 + c + 3] = qv.w;
        sk[row * SKP + c + 0] = kv.x; sk[row * SKP + c + 1] = kv.y;
        sk[row * SKP + c + 2] = kv.z; sk[row * SKP + c + 3] = kv.w;
        sv[row * 128 + c + 0] = vv.x; sv[row * 128 + c + 1] = vv.y;
        sv[row * 128 + c + 2] = vv.z; sv[row * 128 + c + 3] = vv.w;
    }
    if (tid < 64) {
        int s = n * CHK + tid;
        s_g[tid]    = g_in[(size_t)(b * S_ + s) * H_ + h];
        s_beta[tid] = b_in[(size_t)(b * S_ + s) * H_ + h];
    }
    __syncthreads();

    // cumsum of g (serial, tid0) concurrent with row L2 norms (all threads)
    if (tid == 0) {
        float c = 0.f;
        for (int i = 0; i < 64; i++) { c += s_g[i]; s_gcs[i] = c; }
    }
    {
        int row = tid >> 2, part = tid & 3;
        float aq = 0.f, ak = 0.f;
        for (int d = part * 32; d < part * 32 + 32; d++) {
            float a = sq[row * 128 + d]; aq += a * a;
            float c = sk[row * SKP + d]; ak += c * c;
        }
        aq += __shfl_xor_sync(0xffffffff, aq, 1);
        aq += __shfl_xor_sync(0xffffffff, aq, 2);
        ak += __shfl_xor_sync(0xffffffff, ak, 1);
        ak += __shfl_xor_sync(0xffffffff, ak, 2);
        if (part == 0) {
            s_rn[row]      = rsqrtf(aq + 1e-6f) * 0.08838834764831843f; // *Dk^-0.5
            s_rn[64 + row] = rsqrtf(ak + 1e-6f);
        }
    }
    __syncthreads();

    // per-row factor tables (only 64 threads, ~3 expf each — replaces 4K expf)
    if (tid < 64) {
        float gcs = s_gcs[tid];
        float ec  = expf(gcs);
        float eci = expf(-gcs);
        float ec63 = expf(s_gcs[63]);
        float rq = s_rn[tid], rk = s_rn[64 + tid];
        s_fA[tid]  = rq * ec;
        s_fB[tid]  = rk * eci;
        s_gA[tid]  = rk * s_beta[tid] * ec;
        s_fKD[tid] = rk * eci * ec63;
        if (tid == 0) g_egl[t] = ec63;
    }
    __syncthreads();

    // GEMM on RAW data, all scaling in epilogue.
    // A_raw = k.k^T, Q_raw = q.k^T ; paired over d (ffma2).
    const int w = tid >> 5, l = tid & 31;
    {
        u64 accA2[8][2], accQ2[8][2];
        #pragma unroll
        for (int r = 0; r < 8; r++) {
            accA2[r][0] = accA2[r][1] = 0ull;
            accQ2[r][0] = accQ2[r][1] = 0ull;
        }
        for (int d = 0; d < 128; d += 2) {
            u64 k0p = *(const u64*)&sk[l * SKP + d];
            u64 k1p = *(const u64*)&sk[(l + 32) * SKP + d];
            #pragma unroll
            for (int r = 0; r < 8; r++) {
                u64 kip = *(const u64*)&sk[(w * 8 + r) * SKP + d];
                u64 qip = *(const u64*)&sq[(w * 8 + r) * 128 + d];
                accA2[r][0] = ffma2(kip, k0p, accA2[r][0]);
                accA2[r][1] = ffma2(kip, k1p, accA2[r][1]);
                accQ2[r][0] = ffma2(qip, k0p, accQ2[r][0]);
                accQ2[r][1] = ffma2(qip, k1p, accQ2[r][1]);
            }
        }
        float* gattn = g_attn + (size_t)t * (CHK * CHK);
        #pragma unroll
        for (int r = 0; r < 8; r++) {
            int i = w * 8 + r;
            float fAi = s_fA[i], gAi = s_gA[i];
            #pragma unroll
            for (int c2 = 0; c2 < 2; c2++) {
                int jj  = l + c2 * 32;
                float fBj = s_fB[jj];
                gattn[i * 64 + jj] = (i >= jj) ? fold2(accQ2[r][c2]) * fAi * fBj : 0.f;
                if (i > jj)
                    sAp[(i * (i - 1)) / 2 + jj] = fold2(accA2[r][c2]) * gAi * fBj;
            }
        }
    }

    // Flush qg and kd to global from RAW sq/sk (before solve clobbers sq).
    {
        float* gq = g_qg + (size_t)t * (CHK * DK);
        float* gd = g_kd + (size_t)t * (CHK * DK);
        for (int p = tid; p < 8192; p += 256) {
            int row = p >> 7;
            gq[p] = sq[p] * s_fA[row];
        }
        for (int p = tid; p < 4096; p += 256) {
            int rp = p >> 7, k = p & 127;   // rp = c-pair index
            float2 val;
            val.x = sk[(2 * rp)     * SKP + k] * s_fKD[2 * rp];
            val.y = sk[(2 * rp + 1) * SKP + k] * s_fKD[2 * rp + 1];
            *(float2*)&gd[rp * 256 + 2 * k] = val;
        }
    }
    __syncthreads();

    // In-place forward substitution: (I+A) X = [ v*beta | k*gA ]
    // thread c < 128: u column (buffer sv); c >= 128: kcd column (buffer sq).
    {
        const int c   = tid;
        const int cc  = c & 127;
        const bool isV = (c < 128);
        float* buf = isV ? sv : sq;
        int off = 0;   // i*(i-1)/2
        for (int i = 0; i < 64; i++) {
            float acc = isV ? sv[i * 128 + cc] * s_beta[i]
                            : sk[i * SKP + cc] * s_gA[i];
            float a0 = 0.f, a1 = 0.f, a2 = 0.f, a3 = 0.f;
            int m = 0;
            for (; m + 3 < i; m += 4) {
                a0 += sAp[off + m + 0] * buf[(m + 0) * 128 + cc];
                a1 += sAp[off + m + 1] * buf[(m + 1) * 128 + cc];
                a2 += sAp[off + m + 2] * buf[(m + 2) * 128 + cc];
                a3 += sAp[off + m + 3] * buf[(m + 3) * 128 + cc];
            }
            for (; m < i; m++) a0 += sAp[off + m] * buf[m * 128 + cc];
            float val = acc - ((a0 + a1) + (a2 + a3));
            buf[i * 128 + cc] = val;
            if (isV) g_u  [(size_t)t * (CHK * DV) + i * 128 + cc] = val;
            else     g_kcd[(size_t)t * (CHK * DK) + i * 128 + cc] = -val;  // negated
            off += i;
        }
    }
}

// ---------------------------------------------------------------------------
// Phase 2: sequential scan. grid = 128 (32 bh x 4 Dv-blocks), block = 1024.
// No staging: kcd/qg/attn/kd/u streamed via warp-uniform LDG (reuse = 1).
// smem: state (pair-over-k) + vn (pair-over-row) only.
// ---------------------------------------------------------------------------
__global__ __launch_bounds__(1024, 1)
void p2_kernel(float* __restrict__ out)
{
    __shared__ float s_state[4096];   // (k>>1)*64 + 2l + (k&1)
    __shared__ float s_vn[2048];      // (r>>1)*64 + 2l + (r&1)

    const int bx = blockIdx.x;
    const int bh = bx >> 2;
    const int vb = bx & 3;
    const int b  = bh >> 4;
    const int h  = bh & 15;
    const int tid = threadIdx.x;
    const int w = tid >> 5, l = tid & 31;   // 32 warps

    for (int p = tid; p < 4096; p += 1024) s_state[p] = 0.f;
    __syncthreads();

    for (int n = 0; n < NCH; n++) {
        const size_t t = (size_t)bh * NCH + n;
        const float* __restrict__ kcd = g_kcd + t * (CHK * DK);
        const float* __restrict__ qg  = g_qg  + t * (CHK * DK);
        const float* __restrict__ kdp = g_kd  + t * (CHK * DK);
        const float* __restrict__ at  = g_attn + t * (CHK * CHK);
        const float* __restrict__ up  = g_u   + t * (CHK * DV);

        // Phase A: vn = u + (-kcd) @ state ; o1 = qg @ state  (2 rows per warp)
        const int r0 = w * 2;
        u64 sV[2], sO[2];
        float uval[2];
        #pragma unroll
        for (int r = 0; r < 2; r++) {
            sV[r] = 0ull; sO[r] = 0ull;
            uval[r] = up[(r0 + r) * 128 + vb * 32 + l];
        }
        const float* kr0p = kcd + r0 * 128;
        const float* kr1p = kcd + (r0 + 1) * 128;
        const float* qr0p = qg  + r0 * 128;
        const float* qr1p = qg  + (r0 + 1) * 128;
        #pragma unroll 4
        for (int k4 = 0; k4 < 32; k4++) {
            u64 st01 = *(const u64*)&s_state[(2 * k4)     * 64 + 2 * l];
            u64 st23 = *(const u64*)&s_state[(2 * k4 + 1) * 64 + 2 * l];
            ulonglong2 kc0 = *(const ulonglong2*)(kr0p + 4 * k4);
            ulonglong2 kc1 = *(const ulonglong2*)(kr1p + 4 * k4);
            ulonglong2 qc0 = *(const ulonglong2*)(qr0p + 4 * k4);
            ulonglong2 qc1 = *(const ulonglong2*)(qr1p + 4 * k4);
            sV[0] = ffma2(kc0.x, st01, sV[0]);
            sV[0] = ffma2(kc0.y, st23, sV[0]);
            sV[1] = ffma2(kc1.x, st01, sV[1]);
            sV[1] = ffma2(kc1.y, st23, sV[1]);
            sO[0] = ffma2(qc0.x, st01, sO[0]);
            sO[0] = ffma2(qc0.y, st23, sO[0]);
            sO[1] = ffma2(qc1.x, st01, sO[1]);
            sO[1] = ffma2(qc1.y, st23, sO[1]);
        }
        {
            float2 pr;
            pr.x = uval[0] + fold2(sV[0]);
            pr.y = uval[1] + fold2(sV[1]);
            *(float2*)&s_vn[(r0 >> 1) * 64 + 2 * l] = pr;
        }
        __syncthreads();

        // Phase B: o += attn @ vn ; write out
        {
            const float* ar0 = at + r0 * 64;
            const float* ar1 = at + (r0 + 1) * 64;
            #pragma unroll 4
            for (int c4 = 0; c4 < 16; c4++) {
                u64 vn01 = *(const u64*)&s_vn[(2 * c4)     * 64 + 2 * l];
                u64 vn23 = *(const u64*)&s_vn[(2 * c4 + 1) * 64 + 2 * l];
                ulonglong2 a0 = *(const ulonglong2*)(ar0 + 4 * c4);
                ulonglong2 a1 = *(const ulonglong2*)(ar1 + 4 * c4);
                sO[0] = ffma2(a0.x, vn01, sO[0]);
                sO[0] = ffma2(a0.y, vn23, sO[0]);
                sO[1] = ffma2(a1.x, vn01, sO[1]);
                sO[1] = ffma2(a1.y, vn23, sO[1]);
            }
            const size_t obase =
                ((size_t)(b * S_ + n * CHK) * H_ + h) * DV + vb * 32;
            out[obase + (size_t)(r0)     * (H_ * DV) + l] = fold2(sO[0]);
            out[obase + (size_t)(r0 + 1) * (H_ * DV) + l] = fold2(sO[1]);
        }

        // Phase C: state = state*e^{g_last} + kd^T @ vn
        // warp w owns k-rows kr0..kr0+3, col l; kd pair-over-c layout.
        {
            const int kr0 = w * 4;
            u64 s2[4];
            #pragma unroll
            for (int j = 0; j < 4; j++) s2[j] = 0ull;
            #pragma unroll 4
            for (int c2 = 0; c2 < 32; c2++) {
                u64 vnp = *(const u64*)&s_vn[c2 * 64 + 2 * l];
                ulonglong2 kd0 = *(const ulonglong2*)(kdp + c2 * 256 + 2 * kr0);
                ulonglong2 kd1 = *(const ulonglong2*)(kdp + c2 * 256 + 2 * (kr0 + 2));
                s2[0] = ffma2(kd0.x, vnp, s2[0]);
                s2[1] = ffma2(kd0.y, vnp, s2[1]);
                s2[2] = ffma2(kd1.x, vnp, s2[2]);
                s2[3] = ffma2(kd1.y, vnp, s2[3]);
            }
            float eg = g_egl[t];
            #pragma unroll
            for (int j2 = 0; j2 < 2; j2++) {
                float2 old = *(const float2*)&s_state[(kr0 / 2 + j2) * 64 + 2 * l];
                float2 nw;
                nw.x = old.x * eg + fold2(s2[2 * j2]);
                nw.y = old.y * eg + fold2(s2[2 * j2 + 1]);
                *(float2*)&s_state[(kr0 / 2 + j2) * 64 + 2 * l] = nw;
            }
        }
        __syncthreads();
    }
}

// ---------------------------------------------------------------------------
extern "C" void kernel_launch(void* const* d_in, const int* in_sizes, int n_in,
                              void* d_out, int out_size)
{
    const float* q    = (const float*)d_in[0];
    const float* k    = (const float*)d_in[1];
    const float* v    = (const float*)d_in[2];
    const float* g    = (const float*)d_in[3];
    const float* beta = (const float*)d_in[4];
    float* out = (float*)d_out;

    const int p1s = P1_SMEM_FLOATS * 4;
    cudaFuncSetAttribute(p1_kernel, cudaFuncAttributeMaxDynamicSharedMemorySize, p1s);

    p1_kernel<<<NTILE, 256, p1s>>>(q, k, v, g, beta);
    p2_kernel<<<NBH * 4, 1024>>>(out);
}